// round 1
// baseline (speedup 1.0000x reference)
#include <cuda_runtime.h>
#include <cstdint>
#include <math.h>

#define B_ 2
#define T_ 2048
#define BT 4096
#define C_ 1024
#define V_ 32000
#define L_ 4
#define E_ 3
#define H_ 4096
#define NCH 32
#define CHL 64          // T_/NCH
#define SZ (BT*C_)      // 4194304

// Single scratch arena: 12 [BT,C] buffers + 1 [BT,H] + partials + scale + win
// 12*4194304 + 16777216 + 65536 + 4096 + 4096 = 67,182,592 floats (~269 MB)
__device__ float g_scratch[(size_t)SZ * 12 + (size_t)BT * H_ + (size_t)B_ * NCH * C_ + BT + BT];

// ---------------------------------------------------------------------------
// Block reduce
// ---------------------------------------------------------------------------
__device__ __forceinline__ float blockReduceSum(float val) {
    __shared__ float sh[8];
    int lane = threadIdx.x & 31, w = threadIdx.x >> 5;
#pragma unroll
    for (int o = 16; o > 0; o >>= 1) val += __shfl_xor_sync(0xffffffffu, val, o);
    if (lane == 0) sh[w] = val;
    __syncthreads();
    if (w == 0) {
        float v2 = (lane < 8) ? sh[lane] : 0.f;
#pragma unroll
        for (int o = 4; o > 0; o >>= 1) v2 += __shfl_xor_sync(0xffffffffu, v2, o);
        if (lane == 0) sh[0] = v2;
    }
    __syncthreads();
    float r = sh[0];
    __syncthreads();
    return r;
}

// ---------------------------------------------------------------------------
// LayerNorm: one block (256 thr) per row of C_=1024
// ---------------------------------------------------------------------------
__global__ __launch_bounds__(256) void ln_kernel(const float* __restrict__ x,
                                                 float* __restrict__ y,
                                                 const float* __restrict__ g,
                                                 const float* __restrict__ b) {
    int row = blockIdx.x;
    const float* xr = x + (size_t)row * C_;
    int t = threadIdx.x;
    float v0 = xr[t], v1 = xr[t + 256], v2 = xr[t + 512], v3 = xr[t + 768];
    float s = v0 + v1 + v2 + v3;
    s = blockReduceSum(s);
    float mean = s * (1.f / C_);
    float d0 = v0 - mean, d1 = v1 - mean, d2 = v2 - mean, d3 = v3 - mean;
    float s2 = d0 * d0 + d1 * d1 + d2 * d2 + d3 * d3;
    s2 = blockReduceSum(s2);
    float inv = rsqrtf(s2 * (1.f / C_) + 1e-5f);
    float* yr = y + (size_t)row * C_;
    yr[t]       = d0 * inv * g[t]       + b[t];
    yr[t + 256] = d1 * inv * g[t + 256] + b[t + 256];
    yr[t + 512] = d2 * inv * g[t + 512] + b[t + 512];
    yr[t + 768] = d3 * inv * g[t + 768] + b[t + 768];
}

// ---------------------------------------------------------------------------
// Elementwise kernels (grid = SZ/256)
// ---------------------------------------------------------------------------
__global__ __launch_bounds__(256) void embed_kernel(const int* __restrict__ idx,
                                                    const float* __restrict__ emb,
                                                    float* __restrict__ X) {
    int i = blockIdx.x * 256 + threadIdx.x;
    int row = i >> 10, c = i & 1023;
    X[i] = emb[(size_t)idx[row] * C_ + c];
}

__global__ __launch_bounds__(256) void mix_kernel(const float* __restrict__ hs,
                                                  float* __restrict__ mix) {
    int i = blockIdx.x * 256 + threadIdx.x;
    int row = i >> 10;
    int t = row & (T_ - 1);
    float prev = (t == 0) ? 0.f : hs[i - C_];
    mix[i] = 0.5f * (hs[i] + prev);
}

__global__ __launch_bounds__(256) void rs_kernel(const float* __restrict__ r,
                                                 const float* __restrict__ st,
                                                 float* __restrict__ rs) {
    int i = blockIdx.x * 256 + threadIdx.x;
    rs[i] = r[i] * st[i];
}

__global__ __launch_bounds__(256) void select_kernel(float* __restrict__ X,
                                                     const float* __restrict__ e0,
                                                     const float* __restrict__ e1,
                                                     const float* __restrict__ e2,
                                                     const int* __restrict__ win,
                                                     const float* __restrict__ scale) {
    int i = blockIdx.x * 256 + threadIdx.x;
    int row = i >> 10;
    int w = win[row];
    const float* e = (w == 0) ? e0 : ((w == 1) ? e1 : e2);
    X[i] += e[i] * scale[row];
}

// ---------------------------------------------------------------------------
// RWKV state: chunked inclusive scan of k*v over time, divided by (t+1)
// ---------------------------------------------------------------------------
__global__ __launch_bounds__(256) void scan1_kernel(const float* __restrict__ K,
                                                    const float* __restrict__ V,
                                                    float* __restrict__ part) {
    int g = blockIdx.x * 256 + threadIdx.x;      // [0, B_*NCH*C_)
    int c = g & (C_ - 1);
    int ch = (g >> 10) & (NCH - 1);
    int b = g >> 15;
    size_t base = ((size_t)(b * T_ + ch * CHL)) * C_ + c;
    float s = 0.f;
#pragma unroll 4
    for (int j = 0; j < CHL; j++) { s += K[base] * V[base]; base += C_; }
    part[g] = s;
}

__global__ __launch_bounds__(256) void scan2_kernel(float* __restrict__ part) {
    int g = blockIdx.x * 256 + threadIdx.x;      // [0, B_*C_)
    int c = g & (C_ - 1);
    int b = g >> 10;
    float run = 0.f;
#pragma unroll
    for (int ch = 0; ch < NCH; ch++) {
        size_t i = ((size_t)(b * NCH + ch)) * C_ + c;
        float tv = part[i];
        part[i] = run;
        run += tv;
    }
}

__global__ __launch_bounds__(256) void scan3_kernel(const float* __restrict__ K,
                                                    const float* __restrict__ V,
                                                    const float* __restrict__ part,
                                                    float* __restrict__ st) {
    int g = blockIdx.x * 256 + threadIdx.x;
    int c = g & (C_ - 1);
    int ch = (g >> 10) & (NCH - 1);
    int b = g >> 15;
    size_t base = ((size_t)(b * T_ + ch * CHL)) * C_ + c;
    float run = part[g];
#pragma unroll 4
    for (int j = 0; j < CHL; j++) {
        run += K[base] * V[base];
        int tt = ch * CHL + j;
        st[base] = run / (float)(tt + 1);
        base += C_;
    }
}

// ---------------------------------------------------------------------------
// Router: one warp per token; conf=sigmoid(h·wconf_e), aff=h·waff[:,e],
// bid=conf*share+aff, winner=first argmax, scale=conf_w/(conf_w+1e-6)
// ---------------------------------------------------------------------------
__global__ __launch_bounds__(256) void route_kernel(const float* __restrict__ Hh,
                                                    const float* __restrict__ wconf,
                                                    const float* __restrict__ waff,
                                                    const float* __restrict__ shares,
                                                    int* __restrict__ win,
                                                    float* __restrict__ scale) {
    int token = blockIdx.x * 8 + (threadIdx.x >> 5);
    int lane = threadIdx.x & 31;
    const float* h = Hh + (size_t)token * C_;
    float sc0 = 0, sc1 = 0, sc2 = 0, sa0 = 0, sa1 = 0, sa2 = 0;
    for (int c = lane; c < C_; c += 32) {
        float hv = h[c];
        sc0 = fmaf(hv, wconf[c], sc0);
        sc1 = fmaf(hv, wconf[C_ + c], sc1);
        sc2 = fmaf(hv, wconf[2 * C_ + c], sc2);
        sa0 = fmaf(hv, waff[c * E_ + 0], sa0);
        sa1 = fmaf(hv, waff[c * E_ + 1], sa1);
        sa2 = fmaf(hv, waff[c * E_ + 2], sa2);
    }
#pragma unroll
    for (int o = 16; o > 0; o >>= 1) {
        sc0 += __shfl_xor_sync(0xffffffffu, sc0, o);
        sc1 += __shfl_xor_sync(0xffffffffu, sc1, o);
        sc2 += __shfl_xor_sync(0xffffffffu, sc2, o);
        sa0 += __shfl_xor_sync(0xffffffffu, sa0, o);
        sa1 += __shfl_xor_sync(0xffffffffu, sa1, o);
        sa2 += __shfl_xor_sync(0xffffffffu, sa2, o);
    }
    if (lane == 0) {
        float c0 = 1.f / (1.f + expf(-sc0));
        float c1 = 1.f / (1.f + expf(-sc1));
        float c2 = 1.f / (1.f + expf(-sc2));
        float b0 = c0 * shares[0] + sa0;
        float b1 = c1 * shares[1] + sa1;
        float b2 = c2 * shares[2] + sa2;
        int w = 0; float bb = b0, cw = c0;
        if (b1 > bb) { bb = b1; w = 1; cw = c1; }
        if (b2 > bb) { bb = b2; w = 2; cw = c2; }
        win[token] = w;
        scale[token] = cw / (cw + 1e-6f);
    }
}

// ---------------------------------------------------------------------------
// SGEMM: C[M,N] (op)= A[M,K] @ B[K,N], all row-major, fp32.
// 128x128 tile, BK=8, 256 threads, 8x8 per thread.
// M,N multiples of 128; K multiple of 8. Fused epilogues.
// ---------------------------------------------------------------------------
enum { OP_NONE = 0, OP_SIG = 1, OP_RELU = 2, OP_ADD = 3, OP_ADDRELU = 4 };

template <int OP>
__global__ __launch_bounds__(256) void sgemm_kernel(const float* __restrict__ A,
                                                    const float* __restrict__ Bm,
                                                    float* __restrict__ Cm,
                                                    int M, int N, int K) {
    const int BM = 128, BN = 128, BK = 8, TM = 8, TN = 8;
    __shared__ float As[BK][BM];
    __shared__ float Bs[BK][BN];
    int tid = threadIdx.x;
    int bx = blockIdx.x, by = blockIdx.y;
    int arow = tid >> 1, acol = (tid & 1) * 4;
    int brow = tid >> 5, bcol = (tid & 31) * 4;
    const float* Ap = A + (size_t)(by * BM + arow) * K + acol;
    const float* Bp = Bm + (size_t)brow * N + (size_t)bx * BN + bcol;
    float acc[TM][TN];
#pragma unroll
    for (int i = 0; i < TM; i++)
#pragma unroll
        for (int j = 0; j < TN; j++) acc[i][j] = 0.f;
    int ty = tid >> 4, tx = tid & 15;

    for (int k0 = 0; k0 < K; k0 += BK) {
        float4 a4 = *reinterpret_cast<const float4*>(Ap);
        float4 b4 = *reinterpret_cast<const float4*>(Bp);
        As[acol + 0][arow] = a4.x;
        As[acol + 1][arow] = a4.y;
        As[acol + 2][arow] = a4.z;
        As[acol + 3][arow] = a4.w;
        *reinterpret_cast<float4*>(&Bs[brow][bcol]) = b4;
        __syncthreads();
#pragma unroll
        for (int kk = 0; kk < BK; kk++) {
            float ar[TM], br[TN];
            *reinterpret_cast<float4*>(&ar[0]) = *reinterpret_cast<const float4*>(&As[kk][ty * TM]);
            *reinterpret_cast<float4*>(&ar[4]) = *reinterpret_cast<const float4*>(&As[kk][ty * TM + 4]);
            *reinterpret_cast<float4*>(&br[0]) = *reinterpret_cast<const float4*>(&Bs[kk][tx * TN]);
            *reinterpret_cast<float4*>(&br[4]) = *reinterpret_cast<const float4*>(&Bs[kk][tx * TN + 4]);
#pragma unroll
            for (int i = 0; i < TM; i++)
#pragma unroll
                for (int j = 0; j < TN; j++)
                    acc[i][j] = fmaf(ar[i], br[j], acc[i][j]);
        }
        __syncthreads();
        Ap += BK;
        Bp += (size_t)BK * N;
    }

#pragma unroll
    for (int i = 0; i < TM; i++) {
        float* cp = Cm + (size_t)(by * BM + ty * TM + i) * N + (size_t)bx * BN + tx * TN;
#pragma unroll
        for (int j = 0; j < TN; j += 4) {
            float4 v;
            v.x = acc[i][j]; v.y = acc[i][j + 1]; v.z = acc[i][j + 2]; v.w = acc[i][j + 3];
            if (OP == OP_SIG) {
                v.x = 1.f / (1.f + expf(-v.x)); v.y = 1.f / (1.f + expf(-v.y));
                v.z = 1.f / (1.f + expf(-v.z)); v.w = 1.f / (1.f + expf(-v.w));
            } else if (OP == OP_RELU) {
                v.x = fmaxf(v.x, 0.f); v.y = fmaxf(v.y, 0.f);
                v.z = fmaxf(v.z, 0.f); v.w = fmaxf(v.w, 0.f);
            } else if (OP == OP_ADD) {
                float4 o = *reinterpret_cast<const float4*>(cp + j);
                v.x += o.x; v.y += o.y; v.z += o.z; v.w += o.w;
            } else if (OP == OP_ADDRELU) {
                float4 o = *reinterpret_cast<const float4*>(cp + j);
                v.x = fmaxf(v.x + o.x, 0.f); v.y = fmaxf(v.y + o.y, 0.f);
                v.z = fmaxf(v.z + o.z, 0.f); v.w = fmaxf(v.w + o.w, 0.f);
            }
            *reinterpret_cast<float4*>(cp + j) = v;
        }
    }
}

static void gemm(int op, const float* A, const float* Bm, float* Cm, int M, int N, int K) {
    dim3 grid(N / 128, M / 128), block(256);
    switch (op) {
        case OP_NONE:    sgemm_kernel<OP_NONE><<<grid, block>>>(A, Bm, Cm, M, N, K); break;
        case OP_SIG:     sgemm_kernel<OP_SIG><<<grid, block>>>(A, Bm, Cm, M, N, K); break;
        case OP_RELU:    sgemm_kernel<OP_RELU><<<grid, block>>>(A, Bm, Cm, M, N, K); break;
        case OP_ADD:     sgemm_kernel<OP_ADD><<<grid, block>>>(A, Bm, Cm, M, N, K); break;
        case OP_ADDRELU: sgemm_kernel<OP_ADDRELU><<<grid, block>>>(A, Bm, Cm, M, N, K); break;
    }
}

// ---------------------------------------------------------------------------
// Host orchestration
// ---------------------------------------------------------------------------
extern "C" void kernel_launch(void* const* d_in, const int* in_sizes, int n_in,
                              void* d_out, int out_size) {
    (void)in_sizes; (void)n_in; (void)out_size;
    const int*   idx    = (const int*)d_in[0];
    const float* shares = (const float*)d_in[1];
    const float* emb    = (const float*)d_in[2];
    const float* ln1_g  = (const float*)d_in[3];
    const float* ln1_b  = (const float*)d_in[4];
    const float* ln2_g  = (const float*)d_in[5];
    const float* ln2_b  = (const float*)d_in[6];
    const float* Wr     = (const float*)d_in[7];
    const float* Wk     = (const float*)d_in[8];
    const float* Wv     = (const float*)d_in[9];
    const float* Wo     = (const float*)d_in[10];
    const float* W1     = (const float*)d_in[11];
    const float* W2     = (const float*)d_in[12];
    const float* w_conf = (const float*)d_in[13];
    const float* Wl1    = (const float*)d_in[14];
    const float* Wl2    = (const float*)d_in[15];
    /* d_in[16] = W_diff, unused in forward */
    const float* W_aff  = (const float*)d_in[17];
    const float* lnf_g  = (const float*)d_in[18];
    const float* lnf_b  = (const float*)d_in[19];
    const float* head_W = (const float*)d_in[20];

    float* base = nullptr;
    cudaGetSymbolAddress((void**)&base, g_scratch);
    float* X    = base + (size_t)0 * SZ;
    float* HS   = base + (size_t)1 * SZ;
    float* MIXb = base + (size_t)2 * SZ;
    float* R    = base + (size_t)3 * SZ;
    float* Kb   = base + (size_t)4 * SZ;
    float* Vb   = base + (size_t)5 * SZ;
    float* ST   = base + (size_t)6 * SZ;
    float* RS   = base + (size_t)7 * SZ;
    float* Hh   = base + (size_t)8 * SZ;
    float* Ee0  = base + (size_t)9 * SZ;
    float* Ee1  = base + (size_t)10 * SZ;
    float* Ee2  = base + (size_t)11 * SZ;
    float* FF   = base + (size_t)12 * SZ;
    float* PART = FF + (size_t)BT * H_;
    float* SCL  = PART + (size_t)B_ * NCH * C_;
    int*   WIN  = (int*)(SCL + BT);

    const int EW = SZ / 256;  // 16384 blocks for elementwise over [BT,C]

    embed_kernel<<<EW, 256>>>(idx, emb, X);

    for (int l = 0; l < L_; l++) {
        ln_kernel<<<BT, 256>>>(X, HS, ln1_g + (size_t)l * C_, ln1_b + (size_t)l * C_);
        mix_kernel<<<EW, 256>>>(HS, MIXb);
        gemm(OP_SIG,  MIXb, Wr + (size_t)l * C_ * C_, R,  BT, C_, C_);
        gemm(OP_NONE, MIXb, Wk + (size_t)l * C_ * C_, Kb, BT, C_, C_);
        gemm(OP_NONE, MIXb, Wv + (size_t)l * C_ * C_, Vb, BT, C_, C_);
        scan1_kernel<<<(B_ * NCH * C_) / 256, 256>>>(Kb, Vb, PART);
        scan2_kernel<<<(B_ * C_) / 256, 256>>>(PART);
        scan3_kernel<<<(B_ * NCH * C_) / 256, 256>>>(Kb, Vb, PART, ST);
        rs_kernel<<<EW, 256>>>(R, ST, RS);
        gemm(OP_ADD, RS, Wo + (size_t)l * C_ * C_, X, BT, C_, C_);
        ln_kernel<<<BT, 256>>>(X, Hh, ln2_g + (size_t)l * C_, ln2_b + (size_t)l * C_);
        route_kernel<<<BT / 8, 256>>>(Hh, w_conf + (size_t)l * E_ * C_,
                                      W_aff + (size_t)l * C_ * E_,
                                      shares + (size_t)l * E_, WIN, SCL);
        // FFN expert 0
        gemm(OP_RELU, Hh, W1 + (size_t)l * 2 * C_ * H_, FF, BT, H_, C_);
        gemm(OP_NONE, FF, W2 + (size_t)l * 2 * H_ * C_, Ee0, BT, C_, H_);
        // FFN expert 1
        gemm(OP_RELU, Hh, W1 + (size_t)l * 2 * C_ * H_ + (size_t)C_ * H_, FF, BT, H_, C_);
        gemm(OP_NONE, FF, W2 + (size_t)l * 2 * H_ * C_ + (size_t)H_ * C_, Ee1, BT, C_, H_);
        // Linear expert on concat(h, state): split-K over the two halves of Wl1
        gemm(OP_NONE,    Hh, Wl1 + (size_t)l * 2 * C_ * H_, FF, BT, H_, C_);
        gemm(OP_ADDRELU, ST, Wl1 + (size_t)l * 2 * C_ * H_ + (size_t)C_ * H_, FF, BT, H_, C_);
        gemm(OP_NONE,    FF, Wl2 + (size_t)l * H_ * C_, Ee2, BT, C_, H_);
        select_kernel<<<EW, 256>>>(X, Ee0, Ee1, Ee2, WIN, SCL);
    }

    ln_kernel<<<BT, 256>>>(X, HS, lnf_g, lnf_b);
    gemm(OP_NONE, HS, head_W, (float*)d_out, BT, V_, C_);
}